// round 15
// baseline (speedup 1.0000x reference)
#include <cuda_runtime.h>

#define FULL 0xffffffffu

// ---------------- scratch (device globals; no allocations) ----------------
__device__ float g_t1q[4 * 1024 * 128];
__device__ float g_t1k[4 * 1024 * 128];
__device__ float g_t1v[4 * 1024 * 128];
__device__ float g_t2q[4 * 4096 * 128];
__device__ float g_t2k[4 * 4096 * 128];
__device__ float g_t2v[4 * 4096 * 128];

__device__ float g_msg0[4 * 256 * 128];

__device__ float g_ts0[4 * 256 * 8 * 16];
__device__ int   g_ti0[4 * 256 * 8 * 16];

// monotonic total-order key for floats (handles negative sentinels)
__device__ __forceinline__ unsigned xkey(float x) {
    unsigned u = __float_as_uint(x);
    return u ^ ((unsigned)((int)u >> 31) | 0x80000000u);
}

// ============== stage1: level-0 coarse attention + 6 transposes ============
// blocks [0,512): lvl0 (long pole, scheduled first); [512,8192): transposes
__global__ __launch_bounds__(256) void stage1_kernel(
    const float* __restrict__ q0, const float* __restrict__ k0, const float* __restrict__ v0,
    const float* __restrict__ q1, const float* __restrict__ k1, const float* __restrict__ v1,
    const float* __restrict__ q2, const float* __restrict__ k2, const float* __restrict__ v2)
{
    __shared__ float sbuf[8704];   // lvl0: sK 4352 | sA 4096 | sQ 256 ; transpose: 32x33 tile
    int blk = blockIdx.x;

    if (blk >= 512) {
        // ------------- transpose path ([B,C,S] -> [B,S,C]) -------------
        int e0 = blk - 512;
        const float* src; float* dst; int S, e;
        if (e0 < 1536) {
            S = 1024; int w = e0 >> 9; e = e0 & 511;
            src = (w == 0) ? q1 : ((w == 1) ? k1 : v1);
            dst = (w == 0) ? g_t1q : ((w == 1) ? g_t1k : g_t1v);
        } else {
            S = 4096; int bb = e0 - 1536; int w = bb >> 11; e = bb & 2047;
            src = (w == 0) ? q2 : ((w == 1) ? k2 : v2);
            dst = (w == 0) ? g_t2q : ((w == 1) ? g_t2k : g_t2v);
        }
        int nx = S >> 5;
        int x  = e % nx;
        int yc = (e / nx) & 3;
        int b  = e / (nx * 4);
        float (*tile)[33] = reinterpret_cast<float(*)[33]>(sbuf);
        int tx = threadIdx.x & 31, ty = threadIdx.x >> 5;
        const float* sp = src + (size_t)b * 128 * S;
        float* dp = dst + (size_t)b * S * 128;
        int c0 = yc << 5, s0 = x << 5;
#pragma unroll
        for (int i = 0; i < 32; i += 8)
            tile[ty + i][tx] = sp[(size_t)(c0 + ty + i) * S + s0 + tx];
        __syncthreads();
#pragma unroll
        for (int i = 0; i < 32; i += 8)
            dp[(size_t)(s0 + ty + i) * 128 + c0 + tx] = tile[tx][ty + i];
        return;
    }

    // ------------- level-0 path -------------
    int qt = blk & 15;
    int n  = (blk >> 4) & 7;
    int b  = blk >> 7;
    int t  = threadIdx.x;

    float* sK = sbuf;          // 256*17
    float* sA = sbuf + 4352;   // 16*256
    float* sQ = sbuf + 8448;   // 16*16

    const float* kh = k0 + ((size_t)b * 128 + n * 16) * 256;
    const float* qh = q0 + ((size_t)b * 128 + n * 16) * 256;

#pragma unroll
    for (int i = 0; i < 16; i++) {
        int idx = i * 256 + t;
        int d = idx >> 8, s = idx & 255;
        sK[s * 17 + d] = kh[d * 256 + s];
    }
    {
        int qq = t >> 4, d = t & 15;
        sQ[qq * 16 + d] = qh[d * 256 + qt * 16 + qq];
    }
    __syncthreads();

    {
        int qq = t >> 4, spt = t & 15;
#pragma unroll 4
        for (int i = 0; i < 16; i++) {
            int s = spt + 16 * i;
            float acc = 0.f;
#pragma unroll
            for (int d = 0; d < 16; d++) acc = fmaf(sQ[qq * 16 + d], sK[s * 17 + d], acc);
            sA[qq * 256 + s] = acc * 0.25f;
        }
    }
    __syncthreads();

    // softmax + top-16 (two rows per warp, redux-based argmax)
    {
        int warp = t >> 5, lane = t & 31;
        float* rowA = sA + warp * 256;
        float* rowB = sA + (warp + 8) * 256;
        float vA[8], vB[8];
#pragma unroll
        for (int j = 0; j < 8; j++) { vA[j] = rowA[lane + 32 * j]; vB[j] = rowB[lane + 32 * j]; }
        float mA = vA[0], mB = vB[0];
#pragma unroll
        for (int j = 1; j < 8; j++) { mA = fmaxf(mA, vA[j]); mB = fmaxf(mB, vB[j]); }
#pragma unroll
        for (int off = 16; off; off >>= 1) {
            mA = fmaxf(mA, __shfl_xor_sync(FULL, mA, off));
            mB = fmaxf(mB, __shfl_xor_sync(FULL, mB, off));
        }
        float sAcc = 0.f, sBcc = 0.f;
#pragma unroll
        for (int j = 0; j < 8; j++) {
            vA[j] = __expf(vA[j] - mA); sAcc += vA[j];
            vB[j] = __expf(vB[j] - mB); sBcc += vB[j];
        }
#pragma unroll
        for (int off = 16; off; off >>= 1) {
            sAcc += __shfl_xor_sync(FULL, sAcc, off);
            sBcc += __shfl_xor_sync(FULL, sBcc, off);
        }
        float invA = 1.f / sAcc, invB = 1.f / sBcc;
#pragma unroll
        for (int j = 0; j < 8; j++) {
            vA[j] *= invA; rowA[lane + 32 * j] = vA[j];
            vB[j] *= invB; rowB[lane + 32 * j] = vB[j];
        }

        int lA = qt * 16 + warp, lB = qt * 16 + warp + 8;
        size_t obA = (((size_t)b * 256 + lA) * 8 + n) * 16;
        size_t obB = (((size_t)b * 256 + lB) * 8 + n) * 16;
        for (int k = 0; k < 16; k++) {
            float bvA = vA[0]; int bjA = 0;
            float bvB = vB[0]; int bjB = 0;
#pragma unroll
            for (int j = 1; j < 8; j++) {
                if (vA[j] > bvA) { bvA = vA[j]; bjA = j; }
                if (vB[j] > bvB) { bvB = vB[j]; bjB = j; }
            }
            unsigned kA = xkey(bvA), kB = xkey(bvB);
            unsigned wA = __reduce_max_sync(FULL, kA);
            unsigned wB = __reduce_max_sync(FULL, kB);
            unsigned cA = (kA == wA) ? (unsigned)(lane + 32 * bjA) : 0xFFFFFFFFu;
            unsigned cB = (kB == wB) ? (unsigned)(lane + 32 * bjB) : 0xFFFFFFFFu;
            unsigned iA = __reduce_min_sync(FULL, cA);
            unsigned iB = __reduce_min_sync(FULL, cB);
            if (lane == (int)(iA & 31)) {
                int jb = iA >> 5;
#pragma unroll
                for (int j = 0; j < 8; j++) if (j == jb) vA[j] = -1.f;
                rowA[iA] = 0.f;
            }
            if (lane == (int)(iB & 31)) {
                int jb = iB >> 5;
#pragma unroll
                for (int j = 0; j < 8; j++) if (j == jb) vB[j] = -1.f;
                rowB[iB] = 0.f;
            }
            if (lane == 0) {
                g_ts0[obA + k] = __uint_as_float(wA ^ 0x80000000u); g_ti0[obA + k] = (int)iA;
                g_ts0[obB + k] = __uint_as_float(wB ^ 0x80000000u); g_ti0[obB + k] = (int)iB;
            }
        }
    }
    __syncthreads();

    const float* vh = v0 + ((size_t)b * 128 + n * 16) * 256;
#pragma unroll
    for (int i = 0; i < 16; i++) {
        int idx = i * 256 + t;
        int d = idx >> 8, s = idx & 255;
        sK[s * 17 + d] = vh[d * 256 + s];
    }
    __syncthreads();
    {
        int qq = t >> 4, d = t & 15;
        const float* arow = sA + qq * 256;
        float acc0 = 0.f, acc1 = 0.f, acc2 = 0.f, acc3 = 0.f;
#pragma unroll 4
        for (int s = 0; s < 256; s += 4) {
            acc0 = fmaf(arow[s + 0], sK[(s + 0) * 17 + d], acc0);
            acc1 = fmaf(arow[s + 1], sK[(s + 1) * 17 + d], acc1);
            acc2 = fmaf(arow[s + 2], sK[(s + 2) * 17 + d], acc2);
            acc3 = fmaf(arow[s + 3], sK[(s + 3) * 17 + d], acc3);
        }
        g_msg0[((size_t)b * 256 + qt * 16 + qq) * 128 + n * 16 + d] =
            (acc0 + acc1) + (acc2 + acc3);
    }
}

// cooperative gather: 32 keys, 2 keys per warp-instruction (16 lanes x 16 floats)
__device__ __forceinline__ void coop_gather32(const float* __restrict__ base,
                                              const int* keys, float* kv, int lane) {
    int half = lane >> 4, d = lane & 15;
#pragma unroll
    for (int i = 0; i < 32; i += 2) {
        int slot = i + half;
        kv[slot * 17 + d] = base[(size_t)keys[slot] * 128 + d];
    }
}

// ====== merged lvl1 + lvl2 + fusion: one block per lvl1 quad ===============
// grid = B*256, 256 threads (warp per head).
// Phase A: lvl1 (top8 -> smem, msg1 -> smem).  Phase B: 4 lvl2 quads.
// Epilogue: out = msg0 + msg1 + msg2 written directly (smem transpose).
__global__ __launch_bounds__(256) void lvl12_kernel(float* __restrict__ out) {
    __shared__ float sKV [8][32 * 17];   // also aliased as sOut[16][132] at the end
    __shared__ float sA  [8][256];
    __shared__ float sQ  [8][64];
    __shared__ int   sKey[8][64];
    __shared__ float sPs [8][4][8];
    __shared__ int   sPi [8][4][8];
    __shared__ float sM1 [8][4][16];
    __shared__ float sM0 [8][16];

    int blk = blockIdx.x;
    int L = blk & 255, b = blk >> 8;
    int Y = L >> 4, X = L & 15;
    int n = threadIdx.x >> 5, lane = threadIdx.x & 31;
    float* kv = sKV[n];
    float* A  = sA[n];
    float* Qs = sQ[n];
    int* keys = sKey[n];

    // ---------------- Phase A: level-1 ----------------
    int kp = lane >> 2, cj = lane & 3;
    size_t pbase = (((size_t)b * 256 + L) * 8 + n) * 16;
    float ps0 = g_ts0[pbase + kp];
    float ps1 = g_ts0[pbase + 8 + kp];
    int pi0 = g_ti0[pbase + kp];
    int pi1 = g_ti0[pbase + 8 + kp];
    int key0 = (pi0 >> 4) * 64 + (pi0 & 15) * 2 + (cj >> 1) * 32 + (cj & 1);
    int key1 = (pi1 >> 4) * 64 + (pi1 & 15) * 2 + (cj >> 1) * 32 + (cj & 1);
    keys[lane]      = key0;
    keys[32 + lane] = key1;

    if (lane < 16)
        sM0[n][lane] = g_msg0[(((size_t)b * 256 + Y * 16 + X)) * 128 + n * 16 + lane];

    const float* qb = g_t1q + (size_t)b * 1024 * 128 + n * 16;
#pragma unroll
    for (int rep = 0; rep < 2; rep++) {
        int jj = lane + 32 * rep;
        int tq = jj >> 4, d = jj & 15;
        int tok = (2 * Y + (tq >> 1)) * 32 + 2 * X + (tq & 1);
        Qs[jj] = qb[(size_t)tok * 128 + d];
    }
    __syncwarp();

    const float* kb = g_t1k + (size_t)b * 1024 * 128 + n * 16;
    float a0[4], a1[4];

    coop_gather32(kb, keys, kv, lane);
    __syncwarp();
    {
        float row[16];
#pragma unroll
        for (int d = 0; d < 16; d++) row[d] = kv[lane * 17 + d];
#pragma unroll
        for (int tq = 0; tq < 4; tq++) {
            float acc = 0.f;
#pragma unroll
            for (int d = 0; d < 16; d++) acc = fmaf(Qs[tq * 16 + d], row[d], acc);
            a0[tq] = acc * 0.25f;
        }
    }
    __syncwarp();
    coop_gather32(kb, keys + 32, kv, lane);
    __syncwarp();
    {
        float row[16];
#pragma unroll
        for (int d = 0; d < 16; d++) row[d] = kv[lane * 17 + d];
#pragma unroll
        for (int tq = 0; tq < 4; tq++) {
            float acc = 0.f;
#pragma unroll
            for (int d = 0; d < 16; d++) acc = fmaf(Qs[tq * 16 + d], row[d], acc);
            a1[tq] = acc * 0.25f;
        }
    }

    // softmax over 4 children per parent, times parent score
#pragma unroll
    for (int tq = 0; tq < 4; tq++) {
        float m = a0[tq];
        m = fmaxf(m, __shfl_xor_sync(FULL, m, 1));
        m = fmaxf(m, __shfl_xor_sync(FULL, m, 2));
        float e = __expf(a0[tq] - m);
        float s = e;
        s += __shfl_xor_sync(FULL, s, 1);
        s += __shfl_xor_sync(FULL, s, 2);
        a0[tq] = e / s * ps0;

        m = a1[tq];
        m = fmaxf(m, __shfl_xor_sync(FULL, m, 1));
        m = fmaxf(m, __shfl_xor_sync(FULL, m, 2));
        e = __expf(a1[tq] - m);
        s = e;
        s += __shfl_xor_sync(FULL, s, 1);
        s += __shfl_xor_sync(FULL, s, 2);
        a1[tq] = e / s * ps1;

        A[tq * 64 + lane]      = a0[tq];
        A[tq * 64 + 32 + lane] = a1[tq];
    }
    __syncwarp();

    // top-8 of 64 per quad-position -> sPs/sPi (no global round-trip)
    float rv0[4] = {a0[0], a0[1], a0[2], a0[3]};
    float rv1[4] = {a1[0], a1[1], a1[2], a1[3]};
    for (int k = 0; k < 8; k++) {
        unsigned kk[4], win[4], bi[4];
#pragma unroll
        for (int tq = 0; tq < 4; tq++) {
            float bv; unsigned b_;
            if (rv0[tq] >= rv1[tq]) { bv = rv0[tq]; b_ = (unsigned)lane; }
            else                    { bv = rv1[tq]; b_ = (unsigned)(lane + 32); }
            kk[tq] = xkey(bv);
            bi[tq] = b_;
        }
#pragma unroll
        for (int tq = 0; tq < 4; tq++) win[tq] = __reduce_max_sync(FULL, kk[tq]);
#pragma unroll
        for (int tq = 0; tq < 4; tq++) {
            unsigned cand = (kk[tq] == win[tq]) ? bi[tq] : 0xFFFFFFFFu;
            bi[tq] = __reduce_min_sync(FULL, cand);
        }
#pragma unroll
        for (int tq = 0; tq < 4; tq++) {
            unsigned m = bi[tq];
            if (lane == (int)(m & 31)) {
                if (m & 32) rv1[tq] = -1.f; else rv0[tq] = -1.f;
                A[tq * 64 + m] = 0.f;
            }
            if (lane == 0) {
                sPs[n][tq][k] = __uint_as_float(win[tq] ^ 0x80000000u);
                sPi[n][tq][k] = keys[m];
            }
        }
    }
    __syncwarp();

    // msg1: two 32-key halves -> sM1
    const float* vb = g_t1v + (size_t)b * 1024 * 128 + n * 16;
    coop_gather32(vb, keys, kv, lane);
    __syncwarp();
    float acc[2] = {0.f, 0.f};
#pragma unroll
    for (int rep = 0; rep < 2; rep++) {
        int jj = lane + 32 * rep;
        int tq = jj >> 4, d = jj & 15;
#pragma unroll 8
        for (int k = 0; k < 32; k++) acc[rep] = fmaf(A[tq * 64 + k], kv[k * 17 + d], acc[rep]);
    }
    __syncwarp();
    coop_gather32(vb, keys + 32, kv, lane);
    __syncwarp();
#pragma unroll
    for (int rep = 0; rep < 2; rep++) {
        int jj = lane + 32 * rep;
        int tq = jj >> 4, d = jj & 15;
#pragma unroll 8
        for (int k = 0; k < 32; k++) acc[rep] = fmaf(A[tq * 64 + 32 + k], kv[k * 17 + d], acc[rep]);
        sM1[n][tq][d] = acc[rep];
    }
    __syncwarp();

    // ---------------- Phase B: 4 level-2 quads ----------------
    const float* qb2 = g_t2q + (size_t)b * 4096 * 128 + n * 16;
    const float* kb2 = g_t2k + (size_t)b * 4096 * 128 + n * 16;
    const float* vb2 = g_t2v + (size_t)b * 4096 * 128 + n * 16;
    float outv[8];

#pragma unroll
    for (int tq2 = 0; tq2 < 4; tq2++) {
        int ty = tq2 >> 1, tx = tq2 & 1;
        int y2 = 2 * Y + ty, x2 = 2 * X + tx;

        float ps = sPs[n][tq2][kp];
        int   pi = sPi[n][tq2][kp];
        int key = ((pi >> 5) * 2 + (cj >> 1)) * 64 + (pi & 31) * 2 + (cj & 1);
        keys[lane] = key;
#pragma unroll
        for (int rep = 0; rep < 2; rep++) {
            int jj = lane + 32 * rep;
            int tq = jj >> 4, d = jj & 15;
            int tok = (2 * y2 + (tq >> 1)) * 64 + 2 * x2 + (tq & 1);
            Qs[jj] = qb2[(size_t)tok * 128 + d];
        }
        __syncwarp();

        coop_gather32(kb2, keys, kv, lane);
        __syncwarp();

        float a[4];
        {
            float row[16];
#pragma unroll
            for (int d = 0; d < 16; d++) row[d] = kv[lane * 17 + d];
#pragma unroll
            for (int tq = 0; tq < 4; tq++) {
                float s = 0.f;
#pragma unroll
                for (int d = 0; d < 16; d++) s = fmaf(Qs[tq * 16 + d], row[d], s);
                a[tq] = s * 0.25f;
            }
        }
#pragma unroll
        for (int tq = 0; tq < 4; tq++) {
            float m = a[tq];
            m = fmaxf(m, __shfl_xor_sync(FULL, m, 1));
            m = fmaxf(m, __shfl_xor_sync(FULL, m, 2));
            float e = __expf(a[tq] - m);
            float s = e;
            s += __shfl_xor_sync(FULL, s, 1);
            s += __shfl_xor_sync(FULL, s, 2);
            A[tq * 32 + lane] = e / s * ps;   // final level: no masking/topk
        }
        __syncwarp();

        coop_gather32(vb2, keys, kv, lane);
        __syncwarp();

#pragma unroll
        for (int rep = 0; rep < 2; rep++) {
            int jj = lane + 32 * rep;
            int tq = jj >> 4, d = jj & 15;
            float s0 = 0.f, s1 = 0.f;
#pragma unroll 8
            for (int k = 0; k < 32; k += 2) {
                s0 = fmaf(A[tq * 32 + k],     kv[k * 17 + d],       s0);
                s1 = fmaf(A[tq * 32 + k + 1], kv[(k + 1) * 17 + d], s1);
            }
            outv[tq2 * 2 + rep] = ((sM0[n][d] + sM1[n][tq2][d])) + (s0 + s1);
        }
        __syncwarp();
    }

    // ---------------- Epilogue: direct output write ----------------
    __syncthreads();                       // all warps done with kv
    float* sOut = &sKV[0][0];              // alias: 16*132 = 2112 <= 8*544 floats
    int dch = lane & 15;
#pragma unroll
    for (int tq2 = 0; tq2 < 4; tq2++) {
        int ty = tq2 >> 1, tx = tq2 & 1;
#pragma unroll
        for (int rep = 0; rep < 2; rep++) {
            int tq = (lane >> 4) + 2 * rep;
            int p = (2 * ty + (tq >> 1)) * 4 + 2 * tx + (tq & 1);
            sOut[p * 132 + n * 16 + dch] = outv[tq2 * 2 + rep];
        }
    }
    __syncthreads();
    {
        int t = threadIdx.x;
#pragma unroll
        for (int i = 0; i < 2; i++) {
            int idx = i * 256 + t;
            int c = idx & 127, dy = idx >> 7;
            float4 v;
            v.x = sOut[(dy * 4 + 0) * 132 + c];
            v.y = sOut[(dy * 4 + 1) * 132 + c];
            v.z = sOut[(dy * 4 + 2) * 132 + c];
            v.w = sOut[(dy * 4 + 3) * 132 + c];
            float* op = out + ((size_t)b * 128 + c) * 4096 + (size_t)(4 * Y + dy) * 64 + 4 * X;
            *reinterpret_cast<float4*>(op) = v;
        }
    }
}

// ---------------- launch ---------------------------------------------------
extern "C" void kernel_launch(void* const* d_in, const int* in_sizes, int n_in,
                              void* d_out, int out_size) {
    (void)in_sizes; (void)n_in; (void)out_size;
    const float* q0 = (const float*)d_in[0];
    const float* k0 = (const float*)d_in[1];
    const float* v0 = (const float*)d_in[2];
    const float* q1 = (const float*)d_in[3];
    const float* k1 = (const float*)d_in[4];
    const float* v1 = (const float*)d_in[5];
    const float* q2 = (const float*)d_in[6];
    const float* k2 = (const float*)d_in[7];
    const float* v2 = (const float*)d_in[8];

    stage1_kernel<<<8192, 256>>>(q0, k0, v0, q1, k1, v1, q2, k2, v2);
    lvl12_kernel<<<1024, 256>>>((float*)d_out);
}

// round 16
// speedup vs baseline: 1.2356x; 1.2356x over previous
#include <cuda_runtime.h>

#define FULL 0xffffffffu

// ---------------- scratch (device globals; no allocations) ----------------
__device__ float g_t1q[4 * 1024 * 128];
__device__ float g_t1k[4 * 1024 * 128];
__device__ float g_t1v[4 * 1024 * 128];
__device__ float g_t2q[4 * 4096 * 128];
__device__ float g_t2k[4 * 4096 * 128];
__device__ float g_t2v[4 * 4096 * 128];

__device__ float g_msg0[4 * 256  * 128];
__device__ float g_msg1[4 * 1024 * 128];
__device__ float g_msg2[4 * 4096 * 128];

__device__ float g_ts0[4 * 256 * 8 * 16];
__device__ int   g_ti0[4 * 256 * 8 * 16];
__device__ float g_ts1[4 * 1024 * 8 * 8];
__device__ int   g_ti1[4 * 1024 * 8 * 8];

// monotonic total-order key for floats (handles negative sentinels)
__device__ __forceinline__ unsigned xkey(float x) {
    unsigned u = __float_as_uint(x);
    return u ^ ((unsigned)((int)u >> 31) | 0x80000000u);
}

// ============== stage1: level-0 coarse attention + 6 transposes ============
// blocks [0,512): lvl0 (long pole, scheduled first); [512,8192): transposes
__global__ __launch_bounds__(256) void stage1_kernel(
    const float* __restrict__ q0, const float* __restrict__ k0, const float* __restrict__ v0,
    const float* __restrict__ q1, const float* __restrict__ k1, const float* __restrict__ v1,
    const float* __restrict__ q2, const float* __restrict__ k2, const float* __restrict__ v2)
{
    __shared__ float sbuf[8704];   // lvl0: sK 4352 | sA 4096 | sQ 256 ; transpose: 32x33 tile
    int blk = blockIdx.x;

    if (blk >= 512) {
        // ------------- transpose path ([B,C,S] -> [B,S,C]) -------------
        int e0 = blk - 512;
        const float* src; float* dst; int S, e;
        if (e0 < 1536) {
            S = 1024; int w = e0 >> 9; e = e0 & 511;
            src = (w == 0) ? q1 : ((w == 1) ? k1 : v1);
            dst = (w == 0) ? g_t1q : ((w == 1) ? g_t1k : g_t1v);
        } else {
            S = 4096; int bb = e0 - 1536; int w = bb >> 11; e = bb & 2047;
            src = (w == 0) ? q2 : ((w == 1) ? k2 : v2);
            dst = (w == 0) ? g_t2q : ((w == 1) ? g_t2k : g_t2v);
        }
        int nx = S >> 5;
        int x  = e % nx;
        int yc = (e / nx) & 3;
        int b  = e / (nx * 4);
        float (*tile)[33] = reinterpret_cast<float(*)[33]>(sbuf);
        int tx = threadIdx.x & 31, ty = threadIdx.x >> 5;
        const float* sp = src + (size_t)b * 128 * S;
        float* dp = dst + (size_t)b * S * 128;
        int c0 = yc << 5, s0 = x << 5;
#pragma unroll
        for (int i = 0; i < 32; i += 8)
            tile[ty + i][tx] = sp[(size_t)(c0 + ty + i) * S + s0 + tx];
        __syncthreads();
#pragma unroll
        for (int i = 0; i < 32; i += 8)
            dp[(size_t)(s0 + ty + i) * 128 + c0 + tx] = tile[tx][ty + i];
        return;
    }

    // ------------- level-0 path -------------
    int qt = blk & 15;
    int n  = (blk >> 4) & 7;
    int b  = blk >> 7;
    int t  = threadIdx.x;

    float* sK = sbuf;          // 256*17
    float* sA = sbuf + 4352;   // 16*256
    float* sQ = sbuf + 8448;   // 16*16

    const float* kh = k0 + ((size_t)b * 128 + n * 16) * 256;
    const float* qh = q0 + ((size_t)b * 128 + n * 16) * 256;

#pragma unroll
    for (int i = 0; i < 16; i++) {
        int idx = i * 256 + t;
        int d = idx >> 8, s = idx & 255;
        sK[s * 17 + d] = kh[d * 256 + s];
    }
    {
        int qq = t >> 4, d = t & 15;
        sQ[qq * 16 + d] = qh[d * 256 + qt * 16 + qq];
    }
    __syncthreads();

    {
        int qq = t >> 4, spt = t & 15;
#pragma unroll 4
        for (int i = 0; i < 16; i++) {
            int s = spt + 16 * i;
            float acc = 0.f;
#pragma unroll
            for (int d = 0; d < 16; d++) acc = fmaf(sQ[qq * 16 + d], sK[s * 17 + d], acc);
            sA[qq * 256 + s] = acc * 0.25f;
        }
    }
    __syncthreads();

    // softmax + top-16 (two rows per warp, redux-based argmax)
    {
        int warp = t >> 5, lane = t & 31;
        float* rowA = sA + warp * 256;
        float* rowB = sA + (warp + 8) * 256;
        float vA[8], vB[8];
#pragma unroll
        for (int j = 0; j < 8; j++) { vA[j] = rowA[lane + 32 * j]; vB[j] = rowB[lane + 32 * j]; }
        float mA = vA[0], mB = vB[0];
#pragma unroll
        for (int j = 1; j < 8; j++) { mA = fmaxf(mA, vA[j]); mB = fmaxf(mB, vB[j]); }
#pragma unroll
        for (int off = 16; off; off >>= 1) {
            mA = fmaxf(mA, __shfl_xor_sync(FULL, mA, off));
            mB = fmaxf(mB, __shfl_xor_sync(FULL, mB, off));
        }
        float sAcc = 0.f, sBcc = 0.f;
#pragma unroll
        for (int j = 0; j < 8; j++) {
            vA[j] = __expf(vA[j] - mA); sAcc += vA[j];
            vB[j] = __expf(vB[j] - mB); sBcc += vB[j];
        }
#pragma unroll
        for (int off = 16; off; off >>= 1) {
            sAcc += __shfl_xor_sync(FULL, sAcc, off);
            sBcc += __shfl_xor_sync(FULL, sBcc, off);
        }
        float invA = 1.f / sAcc, invB = 1.f / sBcc;
#pragma unroll
        for (int j = 0; j < 8; j++) {
            vA[j] *= invA; rowA[lane + 32 * j] = vA[j];
            vB[j] *= invB; rowB[lane + 32 * j] = vB[j];
        }

        int lA = qt * 16 + warp, lB = qt * 16 + warp + 8;
        size_t obA = (((size_t)b * 256 + lA) * 8 + n) * 16;
        size_t obB = (((size_t)b * 256 + lB) * 8 + n) * 16;
        for (int k = 0; k < 16; k++) {
            float bvA = vA[0]; int bjA = 0;
            float bvB = vB[0]; int bjB = 0;
#pragma unroll
            for (int j = 1; j < 8; j++) {
                if (vA[j] > bvA) { bvA = vA[j]; bjA = j; }
                if (vB[j] > bvB) { bvB = vB[j]; bjB = j; }
            }
            unsigned kA = xkey(bvA), kB = xkey(bvB);
            unsigned wA = __reduce_max_sync(FULL, kA);
            unsigned wB = __reduce_max_sync(FULL, kB);
            unsigned cA = (kA == wA) ? (unsigned)(lane + 32 * bjA) : 0xFFFFFFFFu;
            unsigned cB = (kB == wB) ? (unsigned)(lane + 32 * bjB) : 0xFFFFFFFFu;
            unsigned iA = __reduce_min_sync(FULL, cA);
            unsigned iB = __reduce_min_sync(FULL, cB);
            if (lane == (int)(iA & 31)) {
                int jb = iA >> 5;
#pragma unroll
                for (int j = 0; j < 8; j++) if (j == jb) vA[j] = -1.f;
                rowA[iA] = 0.f;
            }
            if (lane == (int)(iB & 31)) {
                int jb = iB >> 5;
#pragma unroll
                for (int j = 0; j < 8; j++) if (j == jb) vB[j] = -1.f;
                rowB[iB] = 0.f;
            }
            if (lane == 0) {
                g_ts0[obA + k] = __uint_as_float(wA ^ 0x80000000u); g_ti0[obA + k] = (int)iA;
                g_ts0[obB + k] = __uint_as_float(wB ^ 0x80000000u); g_ti0[obB + k] = (int)iB;
            }
        }
    }
    __syncthreads();

    const float* vh = v0 + ((size_t)b * 128 + n * 16) * 256;
#pragma unroll
    for (int i = 0; i < 16; i++) {
        int idx = i * 256 + t;
        int d = idx >> 8, s = idx & 255;
        sK[s * 17 + d] = vh[d * 256 + s];
    }
    __syncthreads();
    {
        int qq = t >> 4, d = t & 15;
        const float* arow = sA + qq * 256;
        float acc0 = 0.f, acc1 = 0.f, acc2 = 0.f, acc3 = 0.f;
#pragma unroll 4
        for (int s = 0; s < 256; s += 4) {
            acc0 = fmaf(arow[s + 0], sK[(s + 0) * 17 + d], acc0);
            acc1 = fmaf(arow[s + 1], sK[(s + 1) * 17 + d], acc1);
            acc2 = fmaf(arow[s + 2], sK[(s + 2) * 17 + d], acc2);
            acc3 = fmaf(arow[s + 3], sK[(s + 3) * 17 + d], acc3);
        }
        g_msg0[((size_t)b * 256 + qt * 16 + qq) * 128 + n * 16 + d] =
            (acc0 + acc1) + (acc2 + acc3);
    }
}

// float4 cooperative gather: 32 keys, 8 keys per warp-instruction
// (4 lanes x float4 per key). kv row stride = 20 floats (16B-aligned slots).
__device__ __forceinline__ void coop_gather32_v4(const float* __restrict__ base,
                                                 const int* keys, float* kv, int lane) {
    int slot8 = lane >> 2, c = lane & 3;
#pragma unroll
    for (int i = 0; i < 32; i += 8) {
        int slot = i + slot8;
        float4 v = reinterpret_cast<const float4*>(base + (size_t)keys[slot] * 128)[c];
        reinterpret_cast<float4*>(kv + slot * 20)[c] = v;
    }
}

// float4 row read: kv row (stride 20) -> 16 registers. Conflict-free.
__device__ __forceinline__ void read_row_v4(const float* kv, int slot, float* row) {
    const float4* r4 = reinterpret_cast<const float4*>(kv + slot * 20);
    float4 x0 = r4[0], x1 = r4[1], x2 = r4[2], x3 = r4[3];
    row[0]  = x0.x; row[1]  = x0.y; row[2]  = x0.z; row[3]  = x0.w;
    row[4]  = x1.x; row[5]  = x1.y; row[6]  = x1.z; row[7]  = x1.w;
    row[8]  = x2.x; row[9]  = x2.y; row[10] = x2.z; row[11] = x2.w;
    row[12] = x3.x; row[13] = x3.y; row[14] = x3.z; row[15] = x3.w;
}

// ---------------- level 1: fine attention (16 parents -> 64 keys) ----------
// grid = B*256 quads, 256 threads (warp per head). Lane owns keys lane, lane+32.
__global__ __launch_bounds__(256) void lvl1_kernel() {
    __shared__ __align__(16) float sKV[8][32 * 20];   // one 32-key half at a time
    __shared__ float sA [8][256];
    __shared__ float sQ [8][64];
    __shared__ int   sKey[8][64];

    int blk = blockIdx.x;
    int L = blk & 255, b = blk >> 8;
    int Y = L >> 4, X = L & 15;
    int n = threadIdx.x >> 5, lane = threadIdx.x & 31;
    float* kv = sKV[n];
    float* A  = sA[n];
    float* Qs = sQ[n];
    int* keys = sKey[n];

    int kp = lane >> 2, cj = lane & 3;
    size_t pbase = (((size_t)b * 256 + L) * 8 + n) * 16;
    float ps0 = g_ts0[pbase + kp];
    float ps1 = g_ts0[pbase + 8 + kp];
    int pi0 = g_ti0[pbase + kp];
    int pi1 = g_ti0[pbase + 8 + kp];
    int key0 = (pi0 >> 4) * 64 + (pi0 & 15) * 2 + (cj >> 1) * 32 + (cj & 1);
    int key1 = (pi1 >> 4) * 64 + (pi1 & 15) * 2 + (cj >> 1) * 32 + (cj & 1);
    keys[lane]      = key0;
    keys[32 + lane] = key1;

    const float* qb = g_t1q + (size_t)b * 1024 * 128 + n * 16;
#pragma unroll
    for (int rep = 0; rep < 2; rep++) {
        int jj = lane + 32 * rep;
        int tq = jj >> 4, d = jj & 15;
        int tok = (2 * Y + (tq >> 1)) * 32 + 2 * X + (tq & 1);
        Qs[jj] = qb[(size_t)tok * 128 + d];
    }
    __syncwarp();

    const float* kb = g_t1k + (size_t)b * 1024 * 128 + n * 16;
    float a0[4], a1[4];

    coop_gather32_v4(kb, keys, kv, lane);
    __syncwarp();
    {
        float row[16];
        read_row_v4(kv, lane, row);
#pragma unroll
        for (int tq = 0; tq < 4; tq++) {
            float acc = 0.f;
#pragma unroll
            for (int d = 0; d < 16; d++) acc = fmaf(Qs[tq * 16 + d], row[d], acc);
            a0[tq] = acc * 0.25f;
        }
    }
    __syncwarp();
    coop_gather32_v4(kb, keys + 32, kv, lane);
    __syncwarp();
    {
        float row[16];
        read_row_v4(kv, lane, row);
#pragma unroll
        for (int tq = 0; tq < 4; tq++) {
            float acc = 0.f;
#pragma unroll
            for (int d = 0; d < 16; d++) acc = fmaf(Qs[tq * 16 + d], row[d], acc);
            a1[tq] = acc * 0.25f;
        }
    }

    // softmax over the 4 children of each parent (cj groups), times parent score
#pragma unroll
    for (int tq = 0; tq < 4; tq++) {
        float m = a0[tq];
        m = fmaxf(m, __shfl_xor_sync(FULL, m, 1));
        m = fmaxf(m, __shfl_xor_sync(FULL, m, 2));
        float e = __expf(a0[tq] - m);
        float s = e;
        s += __shfl_xor_sync(FULL, s, 1);
        s += __shfl_xor_sync(FULL, s, 2);
        a0[tq] = e / s * ps0;

        m = a1[tq];
        m = fmaxf(m, __shfl_xor_sync(FULL, m, 1));
        m = fmaxf(m, __shfl_xor_sync(FULL, m, 2));
        e = __expf(a1[tq] - m);
        s = e;
        s += __shfl_xor_sync(FULL, s, 1);
        s += __shfl_xor_sync(FULL, s, 2);
        a1[tq] = e / s * ps1;

        A[tq * 64 + lane]      = a0[tq];
        A[tq * 64 + 32 + lane] = a1[tq];
    }
    __syncwarp();

    // top-8 of 64 per quad-position; 4 independent chains, redux-based
    size_t ob[4];
#pragma unroll
    for (int tq = 0; tq < 4; tq++) {
        int tok = (2 * Y + (tq >> 1)) * 32 + 2 * X + (tq & 1);
        ob[tq] = (((size_t)b * 1024 + tok) * 8 + n) * 8;
    }
    float rv0[4] = {a0[0], a0[1], a0[2], a0[3]};
    float rv1[4] = {a1[0], a1[1], a1[2], a1[3]};
    for (int k = 0; k < 8; k++) {
        unsigned kk[4], win[4], bi[4];
#pragma unroll
        for (int tq = 0; tq < 4; tq++) {
            float bv; unsigned b_;
            if (rv0[tq] >= rv1[tq]) { bv = rv0[tq]; b_ = (unsigned)lane; }
            else                    { bv = rv1[tq]; b_ = (unsigned)(lane + 32); }
            kk[tq] = xkey(bv);
            bi[tq] = b_;
        }
#pragma unroll
        for (int tq = 0; tq < 4; tq++) win[tq] = __reduce_max_sync(FULL, kk[tq]);
#pragma unroll
        for (int tq = 0; tq < 4; tq++) {
            unsigned cand = (kk[tq] == win[tq]) ? bi[tq] : 0xFFFFFFFFu;
            bi[tq] = __reduce_min_sync(FULL, cand);
        }
#pragma unroll
        for (int tq = 0; tq < 4; tq++) {
            unsigned m = bi[tq];
            if (lane == (int)(m & 31)) {
                if (m & 32) rv1[tq] = -1.f; else rv0[tq] = -1.f;
                A[tq * 64 + m] = 0.f;
            }
            if (lane == 0) {
                g_ts1[ob[tq] + k] = __uint_as_float(win[tq] ^ 0x80000000u);
                g_ti1[ob[tq] + k] = keys[m];
            }
        }
    }
    __syncwarp();

    // V aggregation in two 32-key halves
    const float* vb = g_t1v + (size_t)b * 1024 * 128 + n * 16;
    coop_gather32_v4(vb, keys, kv, lane);
    __syncwarp();
    float acc[2] = {0.f, 0.f};
#pragma unroll
    for (int rep = 0; rep < 2; rep++) {
        int jj = lane + 32 * rep;
        int tq = jj >> 4, d = jj & 15;
#pragma unroll 8
        for (int k = 0; k < 32; k++) acc[rep] = fmaf(A[tq * 64 + k], kv[k * 20 + d], acc[rep]);
    }
    __syncwarp();
    coop_gather32_v4(vb, keys + 32, kv, lane);
    __syncwarp();
#pragma unroll
    for (int rep = 0; rep < 2; rep++) {
        int jj = lane + 32 * rep;
        int tq = jj >> 4, d = jj & 15;
#pragma unroll 8
        for (int k = 0; k < 32; k++) acc[rep] = fmaf(A[tq * 64 + 32 + k], kv[k * 20 + d], acc[rep]);
        int tok = (2 * Y + (tq >> 1)) * 32 + 2 * X + (tq & 1);
        g_msg1[((size_t)b * 1024 + tok) * 128 + n * 16 + d] = acc[rep];
    }
}

// ---------------- level 2: final fine attention (8 parents -> 32 keys) -----
// grid = B*1024 quads, 256 threads (warp per head). Lane owns key=lane.
__global__ __launch_bounds__(256) void lvl2_kernel() {
    __shared__ __align__(16) float sKV[8][32 * 20];
    __shared__ float sA [8][128];
    __shared__ float sQ [8][64];
    __shared__ int   sKey[8][32];

    int blk = blockIdx.x;
    int L = blk & 1023, b = blk >> 10;
    int Y = L >> 5, X = L & 31;
    int n = threadIdx.x >> 5, lane = threadIdx.x & 31;
    float* kv = sKV[n];
    float* A  = sA[n];
    float* Qs = sQ[n];
    int* keys = sKey[n];

    int kp = lane >> 2, cj = lane & 3;
    size_t pb = (((size_t)b * 1024 + L) * 8 + n) * 8 + kp;
    float ps = g_ts1[pb];
    int   pi = g_ti1[pb];
    int key = ((pi >> 5) * 2 + (cj >> 1)) * 64 + (pi & 31) * 2 + (cj & 1);
    keys[lane] = key;

    const float* qb = g_t2q + (size_t)b * 4096 * 128 + n * 16;
#pragma unroll
    for (int rep = 0; rep < 2; rep++) {
        int jj = lane + 32 * rep;
        int tq = jj >> 4, d = jj & 15;
        int tok = (2 * Y + (tq >> 1)) * 64 + 2 * X + (tq & 1);
        Qs[jj] = qb[(size_t)tok * 128 + d];
    }
    __syncwarp();

    const float* kb = g_t2k + (size_t)b * 4096 * 128 + n * 16;
    coop_gather32_v4(kb, keys, kv, lane);
    __syncwarp();

    float a[4];
    {
        float row[16];
        read_row_v4(kv, lane, row);
#pragma unroll
        for (int tq = 0; tq < 4; tq++) {
            float acc = 0.f;
#pragma unroll
            for (int d = 0; d < 16; d++) acc = fmaf(Qs[tq * 16 + d], row[d], acc);
            a[tq] = acc * 0.25f;
        }
    }

#pragma unroll
    for (int tq = 0; tq < 4; tq++) {
        float m = a[tq];
        m = fmaxf(m, __shfl_xor_sync(FULL, m, 1));
        m = fmaxf(m, __shfl_xor_sync(FULL, m, 2));
        float e = __expf(a[tq] - m);
        float s = e;
        s += __shfl_xor_sync(FULL, s, 1);
        s += __shfl_xor_sync(FULL, s, 2);
        A[tq * 32 + lane] = e / s * ps;   // final level: no masking/topk
    }
    __syncwarp();

    const float* vb = g_t2v + (size_t)b * 4096 * 128 + n * 16;
    coop_gather32_v4(vb, keys, kv, lane);
    __syncwarp();

#pragma unroll
    for (int rep = 0; rep < 2; rep++) {
        int jj = lane + 32 * rep;
        int tq = jj >> 4, d = jj & 15;
        float acc0 = 0.f, acc1 = 0.f;
#pragma unroll 8
        for (int k = 0; k < 32; k += 2) {
            acc0 = fmaf(A[tq * 32 + k],     kv[k * 20 + d],       acc0);
            acc1 = fmaf(A[tq * 32 + k + 1], kv[(k + 1) * 20 + d], acc1);
        }
        int tok = (2 * Y + (tq >> 1)) * 64 + 2 * X + (tq & 1);
        g_msg2[((size_t)b * 4096 + tok) * 128 + n * 16 + d] = acc0 + acc1;
    }
}

// ---------------- fusion: upsample-sum all levels, write [B,C,64,64] -------
// grid = 256 (one per (b,y)), 1024 threads
__global__ __launch_bounds__(1024) void fuse_kernel(float* __restrict__ out) {
    __shared__ float sbuf[64 * 129];
    int b = blockIdx.x >> 6, y = blockIdx.x & 63;
    int t = threadIdx.x;
    const float* m0 = g_msg0 + ((size_t)b * 256  + (y >> 2) * 16) * 128;
    const float* m1 = g_msg1 + ((size_t)b * 1024 + (y >> 1) * 32) * 128;
    const float* m2 = g_msg2 + ((size_t)b * 4096 + y * 64) * 128;
#pragma unroll
    for (int i = 0; i < 8; i++) {
        int idx = i * 1024 + t;
        int x = idx >> 7, c = idx & 127;
        sbuf[x * 129 + c] = (m0[(x >> 2) * 128 + c] + m1[(x >> 1) * 128 + c])
                            + m2[x * 128 + c];
    }
    __syncthreads();
    float* ob = out + (size_t)b * 128 * 4096 + (size_t)y * 64;
#pragma unroll
    for (int i = 0; i < 8; i++) {
        int idx = i * 1024 + t;
        int c = idx >> 6, x = idx & 63;
        ob[(size_t)c * 4096 + x] = sbuf[x * 129 + c];
    }
}

// ---------------- launch ---------------------------------------------------
extern "C" void kernel_launch(void* const* d_in, const int* in_sizes, int n_in,
                              void* d_out, int out_size) {
    (void)in_sizes; (void)n_in; (void)out_size;
    const float* q0 = (const float*)d_in[0];
    const float* k0 = (const float*)d_in[1];
    const float* v0 = (const float*)d_in[2];
    const float* q1 = (const float*)d_in[3];
    const float* k1 = (const float*)d_in[4];
    const float* v1 = (const float*)d_in[5];
    const float* q2 = (const float*)d_in[6];
    const float* k2 = (const float*)d_in[7];
    const float* v2 = (const float*)d_in[8];

    stage1_kernel<<<8192, 256>>>(q0, k0, v0, q1, k1, v1, q2, k2, v2);
    lvl1_kernel<<<1024, 256>>>();
    lvl2_kernel<<<4096, 256>>>();
    fuse_kernel<<<256, 1024>>>((float*)d_out);
}

// round 17
// speedup vs baseline: 1.3911x; 1.1258x over previous
#include <cuda_runtime.h>

#define FULL 0xffffffffu

#define CP_COMMIT()  asm volatile("cp.async.commit_group;")
#define CP_WAIT(n)   asm volatile("cp.async.wait_group %0;" :: "n"(n))

// ---------------- scratch (device globals; no allocations) ----------------
__device__ float g_t1q[4 * 1024 * 128];
__device__ float g_t1k[4 * 1024 * 128];
__device__ float g_t1v[4 * 1024 * 128];
__device__ float g_t2q[4 * 4096 * 128];
__device__ float g_t2k[4 * 4096 * 128];
__device__ float g_t2v[4 * 4096 * 128];

__device__ float g_msg0[4 * 256  * 128];
__device__ float g_msg1[4 * 1024 * 128];

__device__ float g_ts0[4 * 256 * 8 * 16];
__device__ int   g_ti0[4 * 256 * 8 * 16];
__device__ float g_ts1[4 * 1024 * 8 * 8];
__device__ int   g_ti1[4 * 1024 * 8 * 8];

// monotonic total-order key for floats (handles negative sentinels)
__device__ __forceinline__ unsigned xkey(float x) {
    unsigned u = __float_as_uint(x);
    return u ^ ((unsigned)((int)u >> 31) | 0x80000000u);
}

// ============== stage1: level-0 coarse attention + 6 transposes ============
// blocks [0,512): lvl0 (long pole, scheduled first); [512,8192): transposes
__global__ __launch_bounds__(256) void stage1_kernel(
    const float* __restrict__ q0, const float* __restrict__ k0, const float* __restrict__ v0,
    const float* __restrict__ q1, const float* __restrict__ k1, const float* __restrict__ v1,
    const float* __restrict__ q2, const float* __restrict__ k2, const float* __restrict__ v2)
{
    __shared__ float sbuf[8704];   // lvl0: sK 4352 | sA 4096 | sQ 256 ; transpose: 32x33 tile
    int blk = blockIdx.x;

    if (blk >= 512) {
        // ------------- transpose path ([B,C,S] -> [B,S,C]) -------------
        int e0 = blk - 512;
        const float* src; float* dst; int S, e;
        if (e0 < 1536) {
            S = 1024; int w = e0 >> 9; e = e0 & 511;
            src = (w == 0) ? q1 : ((w == 1) ? k1 : v1);
            dst = (w == 0) ? g_t1q : ((w == 1) ? g_t1k : g_t1v);
        } else {
            S = 4096; int bb = e0 - 1536; int w = bb >> 11; e = bb & 2047;
            src = (w == 0) ? q2 : ((w == 1) ? k2 : v2);
            dst = (w == 0) ? g_t2q : ((w == 1) ? g_t2k : g_t2v);
        }
        int nx = S >> 5;
        int x  = e % nx;
        int yc = (e / nx) & 3;
        int b  = e / (nx * 4);
        float (*tile)[33] = reinterpret_cast<float(*)[33]>(sbuf);
        int tx = threadIdx.x & 31, ty = threadIdx.x >> 5;
        const float* sp = src + (size_t)b * 128 * S;
        float* dp = dst + (size_t)b * S * 128;
        int c0 = yc << 5, s0 = x << 5;
#pragma unroll
        for (int i = 0; i < 32; i += 8)
            tile[ty + i][tx] = sp[(size_t)(c0 + ty + i) * S + s0 + tx];
        __syncthreads();
#pragma unroll
        for (int i = 0; i < 32; i += 8)
            dp[(size_t)(s0 + ty + i) * 128 + c0 + tx] = tile[tx][ty + i];
        return;
    }

    // ------------- level-0 path -------------
    int qt = blk & 15;
    int n  = (blk >> 4) & 7;
    int b  = blk >> 7;
    int t  = threadIdx.x;

    float* sK = sbuf;          // 256*17
    float* sA = sbuf + 4352;   // 16*256
    float* sQ = sbuf + 8448;   // 16*16

    const float* kh = k0 + ((size_t)b * 128 + n * 16) * 256;
    const float* qh = q0 + ((size_t)b * 128 + n * 16) * 256;

#pragma unroll
    for (int i = 0; i < 16; i++) {
        int idx = i * 256 + t;
        int d = idx >> 8, s = idx & 255;
        sK[s * 17 + d] = kh[d * 256 + s];
    }
    {
        int qq = t >> 4, d = t & 15;
        sQ[qq * 16 + d] = qh[d * 256 + qt * 16 + qq];
    }
    __syncthreads();

    {
        int qq = t >> 4, spt = t & 15;
#pragma unroll 4
        for (int i = 0; i < 16; i++) {
            int s = spt + 16 * i;
            float acc = 0.f;
#pragma unroll
            for (int d = 0; d < 16; d++) acc = fmaf(sQ[qq * 16 + d], sK[s * 17 + d], acc);
            sA[qq * 256 + s] = acc * 0.25f;
        }
    }
    __syncthreads();

    // softmax + top-16 (two rows per warp, redux-based argmax)
    {
        int warp = t >> 5, lane = t & 31;
        float* rowA = sA + warp * 256;
        float* rowB = sA + (warp + 8) * 256;
        float vA[8], vB[8];
#pragma unroll
        for (int j = 0; j < 8; j++) { vA[j] = rowA[lane + 32 * j]; vB[j] = rowB[lane + 32 * j]; }
        float mA = vA[0], mB = vB[0];
#pragma unroll
        for (int j = 1; j < 8; j++) { mA = fmaxf(mA, vA[j]); mB = fmaxf(mB, vB[j]); }
#pragma unroll
        for (int off = 16; off; off >>= 1) {
            mA = fmaxf(mA, __shfl_xor_sync(FULL, mA, off));
            mB = fmaxf(mB, __shfl_xor_sync(FULL, mB, off));
        }
        float sAcc = 0.f, sBcc = 0.f;
#pragma unroll
        for (int j = 0; j < 8; j++) {
            vA[j] = __expf(vA[j] - mA); sAcc += vA[j];
            vB[j] = __expf(vB[j] - mB); sBcc += vB[j];
        }
#pragma unroll
        for (int off = 16; off; off >>= 1) {
            sAcc += __shfl_xor_sync(FULL, sAcc, off);
            sBcc += __shfl_xor_sync(FULL, sBcc, off);
        }
        float invA = 1.f / sAcc, invB = 1.f / sBcc;
#pragma unroll
        for (int j = 0; j < 8; j++) {
            vA[j] *= invA; rowA[lane + 32 * j] = vA[j];
            vB[j] *= invB; rowB[lane + 32 * j] = vB[j];
        }

        int lA = qt * 16 + warp, lB = qt * 16 + warp + 8;
        size_t obA = (((size_t)b * 256 + lA) * 8 + n) * 16;
        size_t obB = (((size_t)b * 256 + lB) * 8 + n) * 16;
        for (int k = 0; k < 16; k++) {
            float bvA = vA[0]; int bjA = 0;
            float bvB = vB[0]; int bjB = 0;
#pragma unroll
            for (int j = 1; j < 8; j++) {
                if (vA[j] > bvA) { bvA = vA[j]; bjA = j; }
                if (vB[j] > bvB) { bvB = vB[j]; bjB = j; }
            }
            unsigned kA = xkey(bvA), kB = xkey(bvB);
            unsigned wA = __reduce_max_sync(FULL, kA);
            unsigned wB = __reduce_max_sync(FULL, kB);
            unsigned cA = (kA == wA) ? (unsigned)(lane + 32 * bjA) : 0xFFFFFFFFu;
            unsigned cB = (kB == wB) ? (unsigned)(lane + 32 * bjB) : 0xFFFFFFFFu;
            unsigned iA = __reduce_min_sync(FULL, cA);
            unsigned iB = __reduce_min_sync(FULL, cB);
            if (lane == (int)(iA & 31)) {
                int jb = iA >> 5;
#pragma unroll
                for (int j = 0; j < 8; j++) if (j == jb) vA[j] = -1.f;
                rowA[iA] = 0.f;
            }
            if (lane == (int)(iB & 31)) {
                int jb = iB >> 5;
#pragma unroll
                for (int j = 0; j < 8; j++) if (j == jb) vB[j] = -1.f;
                rowB[iB] = 0.f;
            }
            if (lane == 0) {
                g_ts0[obA + k] = __uint_as_float(wA ^ 0x80000000u); g_ti0[obA + k] = (int)iA;
                g_ts0[obB + k] = __uint_as_float(wB ^ 0x80000000u); g_ti0[obB + k] = (int)iB;
            }
        }
    }
    __syncthreads();

    const float* vh = v0 + ((size_t)b * 128 + n * 16) * 256;
#pragma unroll
    for (int i = 0; i < 16; i++) {
        int idx = i * 256 + t;
        int d = idx >> 8, s = idx & 255;
        sK[s * 17 + d] = vh[d * 256 + s];
    }
    __syncthreads();
    {
        int qq = t >> 4, d = t & 15;
        const float* arow = sA + qq * 256;
        float acc0 = 0.f, acc1 = 0.f, acc2 = 0.f, acc3 = 0.f;
#pragma unroll 4
        for (int s = 0; s < 256; s += 4) {
            acc0 = fmaf(arow[s + 0], sK[(s + 0) * 17 + d], acc0);
            acc1 = fmaf(arow[s + 1], sK[(s + 1) * 17 + d], acc1);
            acc2 = fmaf(arow[s + 2], sK[(s + 2) * 17 + d], acc2);
            acc3 = fmaf(arow[s + 3], sK[(s + 3) * 17 + d], acc3);
        }
        g_msg0[((size_t)b * 256 + qt * 16 + qq) * 128 + n * 16 + d] =
            (acc0 + acc1) + (acc2 + acc3);
    }
}

// cp.async cooperative gather: 32 keys, 4 lanes x 16B per key, keys via shfl.
// kv row stride = 16 floats (64B).
__device__ __forceinline__ void cp_gather32(const float* __restrict__ base,
                                            int mykey, float* kvrow0, int lane) {
    int slot8 = lane >> 2, c4 = (lane & 3) * 4;
#pragma unroll
    for (int i = 0; i < 32; i += 8) {
        int slot = i + slot8;
        int key = __shfl_sync(FULL, mykey, slot);
        unsigned dst = (unsigned)__cvta_generic_to_shared(kvrow0 + slot * 16 + c4);
        asm volatile("cp.async.cg.shared.global [%0], [%1], 16;"
                     :: "r"(dst), "l"(base + (size_t)key * 128 + c4));
    }
}

// float4 row read: kv row (stride 16) -> 16 registers.
__device__ __forceinline__ void read_row16(const float* kv, int slot, float* row) {
    const float4* r4 = reinterpret_cast<const float4*>(kv + slot * 16);
    float4 x0 = r4[0], x1 = r4[1], x2 = r4[2], x3 = r4[3];
    row[0]  = x0.x; row[1]  = x0.y; row[2]  = x0.z; row[3]  = x0.w;
    row[4]  = x1.x; row[5]  = x1.y; row[6]  = x1.z; row[7]  = x1.w;
    row[8]  = x2.x; row[9]  = x2.y; row[10] = x2.z; row[11] = x2.w;
    row[12] = x3.x; row[13] = x3.y; row[14] = x3.z; row[15] = x3.w;
}

// ---------------- level 1: fine attention (16 parents -> 64 keys) ----------
// grid = B*256 quads, 256 threads (warp per head). Lane owns keys lane, lane+32.
__global__ __launch_bounds__(256) void lvl1_kernel() {
    __shared__ __align__(16) float sKV[8][64 * 16];   // all 64 keys (K, then V)
    __shared__ float sA [8][256];
    __shared__ float sQ [8][64];

    int blk = blockIdx.x;
    int L = blk & 255, b = blk >> 8;
    int Y = L >> 4, X = L & 15;
    int n = threadIdx.x >> 5, lane = threadIdx.x & 31;
    float* kv = sKV[n];
    float* A  = sA[n];
    float* Qs = sQ[n];

    int kp = lane >> 2, cj = lane & 3;
    size_t pbase = (((size_t)b * 256 + L) * 8 + n) * 16;
    float ps0 = g_ts0[pbase + kp];
    float ps1 = g_ts0[pbase + 8 + kp];
    int pi0 = g_ti0[pbase + kp];
    int pi1 = g_ti0[pbase + 8 + kp];
    int key0 = (pi0 >> 4) * 64 + (pi0 & 15) * 2 + (cj >> 1) * 32 + (cj & 1);
    int key1 = (pi1 >> 4) * 64 + (pi1 & 15) * 2 + (cj >> 1) * 32 + (cj & 1);

    // prefetch all 64 K rows
    const float* kb = g_t1k + (size_t)b * 1024 * 128 + n * 16;
    cp_gather32(kb, key0, kv, lane);
    cp_gather32(kb, key1, kv + 32 * 16, lane);
    CP_COMMIT();

    const float* qb = g_t1q + (size_t)b * 1024 * 128 + n * 16;
#pragma unroll
    for (int rep = 0; rep < 2; rep++) {
        int jj = lane + 32 * rep;
        int tq = jj >> 4, d = jj & 15;
        int tok = (2 * Y + (tq >> 1)) * 32 + 2 * X + (tq & 1);
        Qs[jj] = qb[(size_t)tok * 128 + d];
    }
    CP_WAIT(0);
    __syncwarp();

    float a0[4], a1[4];
    {
        float row[16];
        read_row16(kv, lane, row);
#pragma unroll
        for (int tq = 0; tq < 4; tq++) {
            float acc = 0.f;
#pragma unroll
            for (int d = 0; d < 16; d++) acc = fmaf(Qs[tq * 16 + d], row[d], acc);
            a0[tq] = acc * 0.25f;
        }
        read_row16(kv, lane + 32, row);
#pragma unroll
        for (int tq = 0; tq < 4; tq++) {
            float acc = 0.f;
#pragma unroll
            for (int d = 0; d < 16; d++) acc = fmaf(Qs[tq * 16 + d], row[d], acc);
            a1[tq] = acc * 0.25f;
        }
    }
    __syncwarp();   // all K reads done; kv reusable

    // prefetch all 64 V rows (latency hidden behind softmax + topk)
    const float* vb = g_t1v + (size_t)b * 1024 * 128 + n * 16;
    cp_gather32(vb, key0, kv, lane);
    cp_gather32(vb, key1, kv + 32 * 16, lane);
    CP_COMMIT();

    // softmax over the 4 children of each parent (cj groups), times parent score
#pragma unroll
    for (int tq = 0; tq < 4; tq++) {
        float m = a0[tq];
        m = fmaxf(m, __shfl_xor_sync(FULL, m, 1));
        m = fmaxf(m, __shfl_xor_sync(FULL, m, 2));
        float e = __expf(a0[tq] - m);
        float s = e;
        s += __shfl_xor_sync(FULL, s, 1);
        s += __shfl_xor_sync(FULL, s, 2);
        a0[tq] = e / s * ps0;

        m = a1[tq];
        m = fmaxf(m, __shfl_xor_sync(FULL, m, 1));
        m = fmaxf(m, __shfl_xor_sync(FULL, m, 2));
        e = __expf(a1[tq] - m);
        s = e;
        s += __shfl_xor_sync(FULL, s, 1);
        s += __shfl_xor_sync(FULL, s, 2);
        a1[tq] = e / s * ps1;

        A[tq * 64 + lane]      = a0[tq];
        A[tq * 64 + 32 + lane] = a1[tq];
    }
    __syncwarp();

    // top-8 of 64 per quad-position; 4 independent chains, redux-based
    size_t ob[4];
#pragma unroll
    for (int tq = 0; tq < 4; tq++) {
        int tok = (2 * Y + (tq >> 1)) * 32 + 2 * X + (tq & 1);
        ob[tq] = (((size_t)b * 1024 + tok) * 8 + n) * 8;
    }
    float rv0[4] = {a0[0], a0[1], a0[2], a0[3]};
    float rv1[4] = {a1[0], a1[1], a1[2], a1[3]};
    for (int k = 0; k < 8; k++) {
        unsigned kk[4], win[4], bi[4];
#pragma unroll
        for (int tq = 0; tq < 4; tq++) {
            float bv; unsigned b_;
            if (rv0[tq] >= rv1[tq]) { bv = rv0[tq]; b_ = (unsigned)lane; }
            else                    { bv = rv1[tq]; b_ = (unsigned)(lane + 32); }
            kk[tq] = xkey(bv);
            bi[tq] = b_;
        }
#pragma unroll
        for (int tq = 0; tq < 4; tq++) win[tq] = __reduce_max_sync(FULL, kk[tq]);
#pragma unroll
        for (int tq = 0; tq < 4; tq++) {
            unsigned cand = (kk[tq] == win[tq]) ? bi[tq] : 0xFFFFFFFFu;
            bi[tq] = __reduce_min_sync(FULL, cand);
        }
#pragma unroll
        for (int tq = 0; tq < 4; tq++) {
            unsigned m = bi[tq];
            if (lane == (int)(m & 31)) {
                if (m & 32) rv1[tq] = -1.f; else rv0[tq] = -1.f;
                A[tq * 64 + m] = 0.f;
            }
            int klow  = __shfl_sync(FULL, key0, m & 31);
            int khigh = __shfl_sync(FULL, key1, m & 31);
            if (lane == 0) {
                g_ts1[ob[tq] + k] = __uint_as_float(win[tq] ^ 0x80000000u);
                g_ti1[ob[tq] + k] = (m & 32) ? khigh : klow;
            }
        }
    }
    __syncwarp();

    // V aggregation over all 64 keys
    CP_WAIT(0);
    __syncwarp();
#pragma unroll
    for (int rep = 0; rep < 2; rep++) {
        int jj = lane + 32 * rep;
        int tq = jj >> 4, d = jj & 15;
        float s0 = 0.f, s1 = 0.f;
#pragma unroll 8
        for (int k = 0; k < 64; k += 2) {
            s0 = fmaf(A[tq * 64 + k],     kv[k * 16 + d],       s0);
            s1 = fmaf(A[tq * 64 + k + 1], kv[(k + 1) * 16 + d], s1);
        }
        int tok = (2 * Y + (tq >> 1)) * 32 + 2 * X + (tq & 1);
        g_msg1[((size_t)b * 1024 + tok) * 128 + n * 16 + d] = s0 + s1;
    }
}

// ------- level 2 + fusion: final fine attention, writes [B,C,64,64] --------
// grid = B*1024 quads, 256 threads (warp per head). Lane owns key=lane.
__global__ __launch_bounds__(256) void lvl2_kernel(float* __restrict__ out) {
    __shared__ __align__(16) float sKa[8][32 * 16];   // K buffer
    __shared__ __align__(16) float sKb[8][32 * 16];   // V buffer
    __shared__ float sA [8][128];                     // aliased as sOut at the end
    __shared__ float sQ [8][64];

    int blk = blockIdx.x;
    int L = blk & 1023, b = blk >> 10;
    int Y = L >> 5, X = L & 31;
    int n = threadIdx.x >> 5, lane = threadIdx.x & 31;
    float* kvK = sKa[n];
    float* kvV = sKb[n];
    float* A   = sA[n];
    float* Qs  = sQ[n];

    int kp = lane >> 2, cj = lane & 3;
    size_t pb = (((size_t)b * 1024 + L) * 8 + n) * 8 + kp;
    float ps = g_ts1[pb];
    int   pi = g_ti1[pb];
    int key = ((pi >> 5) * 2 + (cj >> 1)) * 64 + (pi & 31) * 2 + (cj & 1);

    // prefetch K and V simultaneously (V latency hidden behind QK+softmax)
    const float* kb2 = g_t2k + (size_t)b * 4096 * 128 + n * 16;
    const float* vb2 = g_t2v + (size_t)b * 4096 * 128 + n * 16;
    cp_gather32(kb2, key, kvK, lane);
    CP_COMMIT();
    cp_gather32(vb2, key, kvV, lane);
    CP_COMMIT();

    // coarse/mid messages for this patch (independent loads, overlap gathers)
    int dch = lane & 15;
    float m0 = g_msg0[((size_t)b * 256 + (Y >> 1) * 16 + (X >> 1)) * 128 + n * 16 + dch];
    float m1 = g_msg1[((size_t)b * 1024 + L) * 128 + n * 16 + dch];
    float m01 = m0 + m1;

    const float* qb2 = g_t2q + (size_t)b * 4096 * 128 + n * 16;
#pragma unroll
    for (int rep = 0; rep < 2; rep++) {
        int jj = lane + 32 * rep;
        int tq = jj >> 4, d = jj & 15;
        int tok = (2 * Y + (tq >> 1)) * 64 + 2 * X + (tq & 1);
        Qs[jj] = qb2[(size_t)tok * 128 + d];
    }
    CP_WAIT(1);
    __syncwarp();

    float a[4];
    {
        float row[16];
        read_row16(kvK, lane, row);
#pragma unroll
        for (int tq = 0; tq < 4; tq++) {
            float acc = 0.f;
#pragma unroll
            for (int d = 0; d < 16; d++) acc = fmaf(Qs[tq * 16 + d], row[d], acc);
            a[tq] = acc * 0.25f;
        }
    }

#pragma unroll
    for (int tq = 0; tq < 4; tq++) {
        float m = a[tq];
        m = fmaxf(m, __shfl_xor_sync(FULL, m, 1));
        m = fmaxf(m, __shfl_xor_sync(FULL, m, 2));
        float e = __expf(a[tq] - m);
        float s = e;
        s += __shfl_xor_sync(FULL, s, 1);
        s += __shfl_xor_sync(FULL, s, 2);
        A[tq * 32 + lane] = e / s * ps;   // final level: no masking/topk
    }
    __syncwarp();

    CP_WAIT(0);
    __syncwarp();

    float outv[2];
#pragma unroll
    for (int rep = 0; rep < 2; rep++) {
        int jj = lane + 32 * rep;
        int tq = jj >> 4, d = jj & 15;
        float acc0 = 0.f, acc1 = 0.f;
#pragma unroll 8
        for (int k = 0; k < 32; k += 2) {
            acc0 = fmaf(A[tq * 32 + k],     kvV[k * 16 + d],       acc0);
            acc1 = fmaf(A[tq * 32 + k + 1], kvV[(k + 1) * 16 + d], acc1);
        }
        outv[rep] = m01 + (acc0 + acc1);
    }

    // epilogue: stage 4 tokens x 128 ch, write [B,C,64,64] as float2 rows
    __syncthreads();                    // A dead across all warps
    float* sOut = &sA[0][0];            // 4*130 = 520 floats <= 8*128
#pragma unroll
    for (int rep = 0; rep < 2; rep++) {
        int tq = (lane >> 4) + 2 * rep;
        sOut[tq * 130 + n * 16 + dch] = outv[rep];
    }
    __syncthreads();
    {
        int t = threadIdx.x;
        int c = t & 127, row = t >> 7;
        float2 v;
        v.x = sOut[(2 * row + 0) * 130 + c];
        v.y = sOut[(2 * row + 1) * 130 + c];
        float* op = out + (((size_t)b * 128 + c) * 64 + (2 * Y + row)) * 64 + 2 * X;
        *reinterpret_cast<float2*>(op) = v;
    }
}

// ---------------- launch ---------------------------------------------------
extern "C" void kernel_launch(void* const* d_in, const int* in_sizes, int n_in,
                              void* d_out, int out_size) {
    (void)in_sizes; (void)n_in; (void)out_size;
    const float* q0 = (const float*)d_in[0];
    const float* k0 = (const float*)d_in[1];
    const float* v0 = (const float*)d_in[2];
    const float* q1 = (const float*)d_in[3];
    const float* k1 = (const float*)d_in[4];
    const float* v1 = (const float*)d_in[5];
    const float* q2 = (const float*)d_in[6];
    const float* k2 = (const float*)d_in[7];
    const float* v2 = (const float*)d_in[8];

    stage1_kernel<<<8192, 256>>>(q0, k0, v0, q1, k1, v1, q2, k2, v2);
    lvl1_kernel<<<1024, 256>>>();
    lvl2_kernel<<<4096, 256>>>((float*)d_out);
}